// round 12
// baseline (speedup 1.0000x reference)
#include <cuda_runtime.h>
#include <cuda_bf16.h>
#include <cstdint>

#define N_NODES 50000
#define N_EDGES 800000
#define DIM     64
#define NLAYERS 3

// A/B row strides in bf16 elems (64 data + 8 pad -> conflict-free LDSM)
#define RA 72
#define RB 72
#define OFF_A_HI 0
#define OFF_A_LO (128 * RA)
#define OFF_B_HI (2 * 128 * RA)
#define OFF_B_LO (2 * 128 * RA + 64 * RB)
#define SMEM_ELEMS (2 * 128 * RA + 2 * 64 * RB)
#define SMEM_BYTES (SMEM_ELEMS * 2)

// Scratch (no cudaMalloc allowed).
__device__ float g_bufA[N_NODES * DIM];
__device__ float g_bufB[N_NODES * DIM];
__device__ float g_agg [N_NODES * DIM];
__device__ float g_tmp [N_NODES * DIM];   // H @ W_root partial

// ---------------------------------------------------------------------------
__global__ void zero_kernel(float4* __restrict__ p, int n4) {
    int i = blockIdx.x * blockDim.x + threadIdx.x;
    if (i < n4) p[i] = make_float4(0.f, 0.f, 0.f, 0.f);
}

// ---------------------------------------------------------------------------
// HYBRID scatter (R11, at the L2 throughput wall — unchanged).
// ---------------------------------------------------------------------------
__global__ __launch_bounds__(128) void scatter_hybrid_kernel(
    const float4* __restrict__ h,
    const int*    __restrict__ src,
    const int*    __restrict__ dst,
    const float*  __restrict__ ew,
    float*        __restrict__ agg)
{
    __shared__ float4 buf[4][8][16];

    const int warp = threadIdx.x >> 5;
    const int lane = threadIdx.x & 31;
    const int sub  = lane >> 4;
    const int l16  = lane & 15;

    const long eBase = ((long)blockIdx.x * 4 + warp) * 16;

    int   myS = 0, myD = 0;
    float myW = 0.f;
    if (lane < 16) {
        myS = __ldg(src + eBase + lane);
        myD = __ldg(dst + eBase + lane);
        myW = __ldg(ew  + eBase + lane);
    }

    #pragma unroll
    for (int it = 0; it < 4; it++) {
        int   k = it * 2 + sub;
        int   s = __shfl_sync(0xffffffffu, myS, k);
        float w = __shfl_sync(0xffffffffu, myW, k);
        float4 v = __ldg(h + (size_t)s * 16 + l16);
        v.x *= w; v.y *= w; v.z *= w; v.w *= w;
        buf[warp][k][l16] = v;
    }
    __syncwarp();
    asm volatile("fence.proxy.async.shared::cta;" ::: "memory");

    if (lane < 8) {
        uint32_t sp = (uint32_t)__cvta_generic_to_shared(&buf[warp][lane][0]);
        float* gp = agg + (size_t)myD * 64;
        asm volatile(
            "cp.reduce.async.bulk.global.shared::cta.bulk_group.add.f32 "
            "[%0], [%1], %2;"
            :: "l"(gp), "r"(sp), "n"(256) : "memory");
        asm volatile("cp.async.bulk.commit_group;" ::: "memory");
    }

    #pragma unroll
    for (int it = 0; it < 4; it++) {
        int   k = 8 + it * 2 + sub;
        int   s = __shfl_sync(0xffffffffu, myS, k);
        int   d = __shfl_sync(0xffffffffu, myD, k);
        float w = __shfl_sync(0xffffffffu, myW, k);
        float4 v = __ldg(h + (size_t)s * 16 + l16);
        float4* p = (float4*)agg + (size_t)d * 16 + l16;
        asm volatile("red.global.add.v4.f32 [%0], {%1,%2,%3,%4};"
                     :: "l"(p), "f"(v.x * w), "f"(v.y * w),
                        "f"(v.z * w), "f"(v.w * w)
                     : "memory");
    }

    if (lane < 8)
        asm volatile("cp.async.bulk.wait_group 0;" ::: "memory");
}

// ---------------------------------------------------------------------------
// Common TC GEMM machinery (bf16-split, fp32 accum)
// ---------------------------------------------------------------------------
__device__ __forceinline__ void ldsm_x4(uint32_t& r0, uint32_t& r1,
                                        uint32_t& r2, uint32_t& r3,
                                        uint32_t addr) {
    asm volatile("ldmatrix.sync.aligned.m8n8.x4.shared.b16 {%0,%1,%2,%3}, [%4];"
                 : "=r"(r0), "=r"(r1), "=r"(r2), "=r"(r3) : "r"(addr));
}

__device__ __forceinline__ void mma_bf16(float* d, const uint32_t* a,
                                         uint32_t b0, uint32_t b1) {
    asm volatile(
        "mma.sync.aligned.m16n8k16.row.col.f32.bf16.bf16.f32 "
        "{%0,%1,%2,%3}, {%4,%5,%6,%7}, {%8,%9}, {%0,%1,%2,%3};"
        : "+f"(d[0]), "+f"(d[1]), "+f"(d[2]), "+f"(d[3])
        : "r"(a[0]), "r"(a[1]), "r"(a[2]), "r"(a[3]), "r"(b0), "r"(b1));
}

__device__ __forceinline__ void split2(float a, float b,
                                       __nv_bfloat162& h, __nv_bfloat162& l) {
    __nv_bfloat16 ha = __float2bfloat16_rn(a);
    __nv_bfloat16 hb = __float2bfloat16_rn(b);
    float la = a - __bfloat162float(ha);
    float lb = b - __bfloat162float(hb);
    h = __halves2bfloat162(ha, hb);
    l = __halves2bfloat162(__float2bfloat16_rn(la), __float2bfloat16_rn(lb));
}

// Stage A (128 x 64 fp32 -> hi/lo bf16 SMEM) and W^T; optionally zero S.
__device__ __forceinline__ void stage_AB(
    const float* S, const float* W, float* zeroS,
    __nv_bfloat16* sm, int tid, int rowBase)
{
    #pragma unroll
    for (int i = 0; i < 8; i++) {
        int q   = tid + i * 256;
        int row = q >> 4;
        int c4  = (q & 15) * 4;
        int gr  = rowBase + row;
        float4 v = make_float4(0.f, 0.f, 0.f, 0.f);
        if (gr < N_NODES) v = *(const float4*)(S + (size_t)gr * 64 + c4);
        __nv_bfloat162 h0, l0, h1, l1;
        split2(v.x, v.y, h0, l0);
        split2(v.z, v.w, h1, l1);
        int base = row * RA + c4;
        *(__nv_bfloat162*)&sm[OFF_A_HI + base]     = h0;
        *(__nv_bfloat162*)&sm[OFF_A_HI + base + 2] = h1;
        *(__nv_bfloat162*)&sm[OFF_A_LO + base]     = l0;
        *(__nv_bfloat162*)&sm[OFF_A_LO + base + 2] = l1;
        if (zeroS && gr < N_NODES)
            *(float4*)(zeroS + (size_t)gr * 64 + c4) =
                make_float4(0.f, 0.f, 0.f, 0.f);
    }
    #pragma unroll
    for (int i = 0; i < 16; i++) {
        int q = tid + i * 256;
        int k = q >> 6;
        int n = q & 63;
        float w = __ldg(W + k * 64 + n);
        __nv_bfloat16 hw = __float2bfloat16_rn(w);
        float lw = w - __bfloat162float(hw);
        sm[OFF_B_HI + n * RB + k] = hw;
        sm[OFF_B_LO + n * RB + k] = __float2bfloat16_rn(lw);
    }
}

// 3-combo (hi*hi, hi*lo, lo*hi) K=64 MMA into acc[2][4][4].
__device__ __forceinline__ void compute_tile(
    float acc[2][4][4], uint32_t sbase,
    int aRow, int aColB, int bRow, int bColB)
{
    const int aOffC[3] = { OFF_A_HI, OFF_A_HI, OFF_A_LO };
    const int bOffC[3] = { OFF_B_HI, OFF_B_LO, OFF_B_HI };
    #pragma unroll
    for (int c = 0; c < 3; c++) {
        uint32_t aBase = sbase + (uint32_t)(aOffC[c] + aRow * RA + aColB) * 2;
        uint32_t bBase = sbase + (uint32_t)(bOffC[c] + bRow * RB + bColB) * 2;
        #pragma unroll
        for (int ks = 0; ks < 4; ks++) {
            uint32_t a[2][4], b[2][4];
            #pragma unroll
            for (int mi = 0; mi < 2; mi++)
                ldsm_x4(a[mi][0], a[mi][1], a[mi][2], a[mi][3],
                        aBase + (uint32_t)(mi * 16 * RA + ks * 16) * 2);
            #pragma unroll
            for (int nb = 0; nb < 2; nb++)
                ldsm_x4(b[nb][0], b[nb][1], b[nb][2], b[nb][3],
                        bBase + (uint32_t)(nb * 16 * RB + ks * 16) * 2);
            #pragma unroll
            for (int mi = 0; mi < 2; mi++)
                #pragma unroll
                for (int ni = 0; ni < 4; ni++)
                    mma_bf16(acc[mi][ni], a[mi],
                             b[ni >> 1][(ni & 1) * 2],
                             b[ni >> 1][(ni & 1) * 2 + 1]);
        }
    }
}

// ---------------------------------------------------------------------------
// Root GEMM (side stream, overlaps scatter): tmp = H @ Wroot (raw store)
// ---------------------------------------------------------------------------
__global__ __launch_bounds__(256, 3) void gemm_root_kernel(
    const float* __restrict__ H,
    const float* __restrict__ Wroot,
    float*       __restrict__ tmp)
{
    extern __shared__ __nv_bfloat16 sm[];
    uint32_t sbase;
    asm("{.reg .u64 t; cvta.to.shared.u64 t, %1; cvt.u32.u64 %0, t;}"
        : "=r"(sbase) : "l"(sm));

    const int tid  = threadIdx.x;
    const int lane = tid & 31;
    const int warp = tid >> 5;
    const int wm   = warp >> 1;
    const int wn   = warp & 1;
    const int rowBase = blockIdx.x * 128;

    float acc[2][4][4];
    #pragma unroll
    for (int mi = 0; mi < 2; mi++)
        #pragma unroll
        for (int ni = 0; ni < 4; ni++)
            #pragma unroll
            for (int k = 0; k < 4; k++) acc[mi][ni][k] = 0.f;

    stage_AB(H, Wroot, nullptr, sm, tid, rowBase);
    __syncthreads();

    const int m0 = wm * 32, n0 = wn * 32;
    compute_tile(acc, sbase,
                 m0 + (lane & 15), (lane >> 4) * 8,
                 n0 + (lane & 7) + ((lane >> 4) * 8), ((lane >> 3) & 1) * 8);

    #pragma unroll
    for (int mi = 0; mi < 2; mi++)
        #pragma unroll
        for (int ni = 0; ni < 4; ni++) {
            int col = n0 + ni * 8 + (lane & 3) * 2;
            int r0  = rowBase + m0 + mi * 16 + (lane >> 2);
            #pragma unroll
            for (int hh = 0; hh < 2; hh++) {
                int r = r0 + hh * 8;
                if (r >= N_NODES) continue;
                *(float2*)(tmp + (size_t)r * 64 + col) =
                    make_float2(acc[mi][ni][hh * 2], acc[mi][ni][hh * 2 + 1]);
            }
        }
}

// ---------------------------------------------------------------------------
// Rel GEMM (main stream, after join): out = AGG@Wrel + tmp + bias (+tanh)
// ---------------------------------------------------------------------------
__global__ __launch_bounds__(256, 3) void gemm_rel_kernel(
    float*                    AGG,
    const float* __restrict__ Wrel,
    const float* __restrict__ bias,
    const float* __restrict__ tmp,
    float*       __restrict__ out,
    int doTanh, int doZero)
{
    extern __shared__ __nv_bfloat16 sm[];
    uint32_t sbase;
    asm("{.reg .u64 t; cvta.to.shared.u64 t, %1; cvt.u32.u64 %0, t;}"
        : "=r"(sbase) : "l"(sm));

    const int tid  = threadIdx.x;
    const int lane = tid & 31;
    const int warp = tid >> 5;
    const int wm   = warp >> 1;
    const int wn   = warp & 1;
    const int rowBase = blockIdx.x * 128;

    float acc[2][4][4];
    #pragma unroll
    for (int mi = 0; mi < 2; mi++)
        #pragma unroll
        for (int ni = 0; ni < 4; ni++)
            #pragma unroll
            for (int k = 0; k < 4; k++) acc[mi][ni][k] = 0.f;

    stage_AB(AGG, Wrel, doZero ? AGG : nullptr, sm, tid, rowBase);
    __syncthreads();

    const int m0 = wm * 32, n0 = wn * 32;
    compute_tile(acc, sbase,
                 m0 + (lane & 15), (lane >> 4) * 8,
                 n0 + (lane & 7) + ((lane >> 4) * 8), ((lane >> 3) & 1) * 8);

    #pragma unroll
    for (int mi = 0; mi < 2; mi++)
        #pragma unroll
        for (int ni = 0; ni < 4; ni++) {
            int col = n0 + ni * 8 + (lane & 3) * 2;
            float b0 = __ldg(bias + col);
            float b1 = __ldg(bias + col + 1);
            int r0 = rowBase + m0 + mi * 16 + (lane >> 2);
            #pragma unroll
            for (int hh = 0; hh < 2; hh++) {
                int r = r0 + hh * 8;
                if (r >= N_NODES) continue;
                float2 t = *(const float2*)(tmp + (size_t)r * 64 + col);
                float v0 = acc[mi][ni][hh * 2]     + t.x + b0;
                float v1 = acc[mi][ni][hh * 2 + 1] + t.y + b1;
                if (doTanh) {
                    asm("tanh.approx.f32 %0, %0;" : "+f"(v0));
                    asm("tanh.approx.f32 %0, %0;" : "+f"(v1));
                }
                *(float2*)(out + (size_t)r * 64 + col) = make_float2(v0, v1);
            }
        }
}

// ---------------------------------------------------------------------------
// Launcher: fork/join — root-GEMM on a side stream concurrent with scatter.
// ---------------------------------------------------------------------------
extern "C" void kernel_launch(void* const* d_in, const int* in_sizes, int n_in,
                              void* d_out, int out_size)
{
    const float* x      = (const float*)d_in[0];
    const int*   eidx   = (const int*)  d_in[1];
    const float* ew     = (const float*)d_in[2];
    const float* W_rel  = (const float*)d_in[3];
    const float* b_rel  = (const float*)d_in[4];
    const float* W_root = (const float*)d_in[5];
    float* out = (float*)d_out;

    const int* src = eidx;
    const int* dst = eidx + N_EDGES;

    float *pA, *pB, *pAgg, *pTmp;
    cudaGetSymbolAddress((void**)&pA,   g_bufA);
    cudaGetSymbolAddress((void**)&pB,   g_bufB);
    cudaGetSymbolAddress((void**)&pAgg, g_agg);
    cudaGetSymbolAddress((void**)&pTmp, g_tmp);

    static cudaStream_t sSide = nullptr;
    static cudaEvent_t  evFork[NLAYERS], evJoin[NLAYERS];
    static bool initDone = false;
    if (!initDone) {
        cudaFuncSetAttribute(gemm_root_kernel,
                             cudaFuncAttributeMaxDynamicSharedMemorySize,
                             SMEM_BYTES);
        cudaFuncSetAttribute(gemm_rel_kernel,
                             cudaFuncAttributeMaxDynamicSharedMemorySize,
                             SMEM_BYTES);
        cudaStreamCreateWithFlags(&sSide, cudaStreamNonBlocking);
        for (int i = 0; i < NLAYERS; i++) {
            cudaEventCreateWithFlags(&evFork[i], cudaEventDisableTiming);
            cudaEventCreateWithFlags(&evJoin[i], cudaEventDisableTiming);
        }
        initDone = true;
    }

    const int n4 = N_NODES * (DIM / 4);
    const int zeroBlocks    = (n4 + 255) / 256;
    const int scatterBlocks = N_EDGES / (4 * 16);      // 12500
    const int gemmBlocks    = (N_NODES + 127) / 128;   // 391

    zero_kernel<<<zeroBlocks, 256>>>((float4*)pAgg, n4);

    const float* hprev = x;
    for (int layer = 0; layer < NLAYERS; layer++) {
        float* hnext = (layer == NLAYERS - 1) ? out : ((layer == 0) ? pA : pB);

        // Fork: root-GEMM on side stream, concurrent with the scatter.
        cudaEventRecord(evFork[layer], 0);
        cudaStreamWaitEvent(sSide, evFork[layer], 0);
        gemm_root_kernel<<<gemmBlocks, 256, SMEM_BYTES, sSide>>>(
            hprev, W_root + (size_t)layer * DIM * DIM, pTmp);
        cudaEventRecord(evJoin[layer], sSide);

        scatter_hybrid_kernel<<<scatterBlocks, 128>>>(
            (const float4*)hprev, src, dst, ew, pAgg);

        // Join: rel-GEMM needs both scatter (main) and root-GEMM (side).
        cudaStreamWaitEvent(0, evJoin[layer], 0);
        gemm_rel_kernel<<<gemmBlocks, 256, SMEM_BYTES>>>(
            pAgg,
            W_rel + (size_t)layer * DIM * DIM,
            b_rel + (size_t)layer * DIM,
            pTmp, hnext,
            layer == NLAYERS - 1 ? 1 : 0,
            layer == NLAYERS - 1 ? 0 : 1);

        hprev = hnext;
    }
}

// round 14
// speedup vs baseline: 1.0462x; 1.0462x over previous
#include <cuda_runtime.h>
#include <cuda_bf16.h>
#include <cstdint>

#define N_NODES 50000
#define N_EDGES 800000
#define DIM     64
#define NLAYERS 3

// A/B row strides in bf16 elems (64 data + 8 pad -> conflict-free LDSM)
#define RA 72
#define RB 72
// 64-row tile SMEM layout (bf16 elems)
#define OFF_A_HI 0
#define OFF_A_LO (64 * RA)
#define OFF_B_HI (2 * 64 * RA)
#define OFF_B_LO (2 * 64 * RA + 64 * RB)
#define SMEM_ELEMS (2 * 64 * RA + 2 * 64 * RB)
#define SMEM_BYTES (SMEM_ELEMS * 2)       // 36,864 B

// Scratch (no cudaMalloc allowed).
__device__ float g_bufA[N_NODES * DIM];
__device__ float g_bufB[N_NODES * DIM];
__device__ float g_agg [N_NODES * DIM];

// ---------------------------------------------------------------------------
__global__ void zero_kernel(float4* __restrict__ p, int n4) {
    int i = blockIdx.x * blockDim.x + threadIdx.x;
    if (i < n4) p[i] = make_float4(0.f, 0.f, 0.f, 0.f);
}

// ---------------------------------------------------------------------------
// HYBRID scatter (R11, at the L2 throughput wall — unchanged).
// ---------------------------------------------------------------------------
__global__ __launch_bounds__(128) void scatter_hybrid_kernel(
    const float4* __restrict__ h,
    const int*    __restrict__ src,
    const int*    __restrict__ dst,
    const float*  __restrict__ ew,
    float*        __restrict__ agg)
{
    __shared__ float4 buf[4][8][16];

    const int warp = threadIdx.x >> 5;
    const int lane = threadIdx.x & 31;
    const int sub  = lane >> 4;
    const int l16  = lane & 15;

    const long eBase = ((long)blockIdx.x * 4 + warp) * 16;

    int   myS = 0, myD = 0;
    float myW = 0.f;
    if (lane < 16) {
        myS = __ldg(src + eBase + lane);
        myD = __ldg(dst + eBase + lane);
        myW = __ldg(ew  + eBase + lane);
    }

    #pragma unroll
    for (int it = 0; it < 4; it++) {
        int   k = it * 2 + sub;
        int   s = __shfl_sync(0xffffffffu, myS, k);
        float w = __shfl_sync(0xffffffffu, myW, k);
        float4 v = __ldg(h + (size_t)s * 16 + l16);
        v.x *= w; v.y *= w; v.z *= w; v.w *= w;
        buf[warp][k][l16] = v;
    }
    __syncwarp();
    asm volatile("fence.proxy.async.shared::cta;" ::: "memory");

    if (lane < 8) {
        uint32_t sp = (uint32_t)__cvta_generic_to_shared(&buf[warp][lane][0]);
        float* gp = agg + (size_t)myD * 64;
        asm volatile(
            "cp.reduce.async.bulk.global.shared::cta.bulk_group.add.f32 "
            "[%0], [%1], %2;"
            :: "l"(gp), "r"(sp), "n"(256) : "memory");
        asm volatile("cp.async.bulk.commit_group;" ::: "memory");
    }

    #pragma unroll
    for (int it = 0; it < 4; it++) {
        int   k = 8 + it * 2 + sub;
        int   s = __shfl_sync(0xffffffffu, myS, k);
        int   d = __shfl_sync(0xffffffffu, myD, k);
        float w = __shfl_sync(0xffffffffu, myW, k);
        float4 v = __ldg(h + (size_t)s * 16 + l16);
        float4* p = (float4*)agg + (size_t)d * 16 + l16;
        asm volatile("red.global.add.v4.f32 [%0], {%1,%2,%3,%4};"
                     :: "l"(p), "f"(v.x * w), "f"(v.y * w),
                        "f"(v.z * w), "f"(v.w * w)
                     : "memory");
    }

    if (lane < 8)
        asm volatile("cp.async.bulk.wait_group 0;" ::: "memory");
}

// ---------------------------------------------------------------------------
// TC dual GEMM, bf16-split, fp32 accum; 64-row tile, 256 thr, 4 CTAs/SM.
// PDL: stage 0 (H@Wroot) pre-sync; stage 1 (AGG@Wrel) gated.
// ---------------------------------------------------------------------------
__device__ __forceinline__ void ldsm_x4(uint32_t& r0, uint32_t& r1,
                                        uint32_t& r2, uint32_t& r3,
                                        uint32_t addr) {
    asm volatile("ldmatrix.sync.aligned.m8n8.x4.shared.b16 {%0,%1,%2,%3}, [%4];"
                 : "=r"(r0), "=r"(r1), "=r"(r2), "=r"(r3) : "r"(addr));
}

__device__ __forceinline__ void mma_bf16(float* d, const uint32_t* a,
                                         uint32_t b0, uint32_t b1) {
    asm volatile(
        "mma.sync.aligned.m16n8k16.row.col.f32.bf16.bf16.f32 "
        "{%0,%1,%2,%3}, {%4,%5,%6,%7}, {%8,%9}, {%0,%1,%2,%3};"
        : "+f"(d[0]), "+f"(d[1]), "+f"(d[2]), "+f"(d[3])
        : "r"(a[0]), "r"(a[1]), "r"(a[2]), "r"(a[3]), "r"(b0), "r"(b1));
}

__device__ __forceinline__ void split2(float a, float b,
                                       __nv_bfloat162& h, __nv_bfloat162& l) {
    __nv_bfloat16 ha = __float2bfloat16_rn(a);
    __nv_bfloat16 hb = __float2bfloat16_rn(b);
    float la = a - __bfloat162float(ha);
    float lb = b - __bfloat162float(hb);
    h = __halves2bfloat162(ha, hb);
    l = __halves2bfloat162(__float2bfloat16_rn(la), __float2bfloat16_rn(lb));
}

__global__ __launch_bounds__(256, 4) void gemm_tc_kernel(
    const float* __restrict__ H,
    float*                    AGG,     // no restrict: loaded then zeroed
    const float* __restrict__ Wroot,   // [64][64]
    const float* __restrict__ Wrel,    // [64][64]
    const float* __restrict__ bias,    // [64]
    float*       __restrict__ out,
    int doTanh, int doZero)
{
    extern __shared__ __nv_bfloat16 sm[];
    uint32_t sbase;
    asm("{.reg .u64 t; cvta.to.shared.u64 t, %1; cvt.u32.u64 %0, t;}"
        : "=r"(sbase) : "l"(sm));

    const int tid     = threadIdx.x;
    const int lane    = tid & 31;
    const int warp    = tid >> 5;
    const int wm      = warp & 3;        // 0..3 -> 16-row strip
    const int wn      = warp >> 2;       // 0..1 -> 32-col strip
    const int rowBase = blockIdx.x * 64;

    float acc[4][4];
    #pragma unroll
    for (int ni = 0; ni < 4; ni++)
        #pragma unroll
        for (int k = 0; k < 4; k++) acc[ni][k] = 0.f;

    const int m0 = wm * 16;
    const int n0 = wn * 32;
    const int aRow  = m0 + (lane & 15);
    const int aColB = (lane >> 4) * 8;
    const int bRow  = n0 + (lane & 7) + ((lane >> 4) * 8);
    const int bColB = ((lane >> 3) & 1) * 8;

    #pragma unroll 1
    for (int s = 0; s < 2; s++) {
        __syncthreads();

        // Gate only the scatter-dependent stage.
        if (s == 1) cudaGridDependencySynchronize();

        // Stage A: 64 rows x 64 cols fp32 -> bf16 hi/lo
        const float* S = s ? (const float*)AGG : H;
        #pragma unroll
        for (int i = 0; i < 4; i++) {
            int q   = tid + i * 256;        // 0..1023
            int row = q >> 4;               // 0..63
            int c4  = (q & 15) * 4;
            int gr  = rowBase + row;
            float4 v = make_float4(0.f, 0.f, 0.f, 0.f);
            if (gr < N_NODES) v = *(const float4*)(S + (size_t)gr * 64 + c4);
            __nv_bfloat162 h0, l0, h1, l1;
            split2(v.x, v.y, h0, l0);
            split2(v.z, v.w, h1, l1);
            int base = row * RA + c4;
            *(__nv_bfloat162*)&sm[OFF_A_HI + base]     = h0;
            *(__nv_bfloat162*)&sm[OFF_A_HI + base + 2] = h1;
            *(__nv_bfloat162*)&sm[OFF_A_LO + base]     = l0;
            *(__nv_bfloat162*)&sm[OFF_A_LO + base + 2] = l1;
            if (s == 1 && doZero && gr < N_NODES)
                *(float4*)(AGG + (size_t)gr * 64 + c4) =
                    make_float4(0.f, 0.f, 0.f, 0.f);
        }

        // Stage B: W^T
        const float* Wm = s ? Wrel : Wroot;
        #pragma unroll
        for (int i = 0; i < 16; i++) {
            int q = tid + i * 256;          // 0..4095
            int k = q >> 6;
            int n = q & 63;
            float w = __ldg(Wm + k * 64 + n);
            __nv_bfloat16 hw = __float2bfloat16_rn(w);
            float lw = w - __bfloat162float(hw);
            sm[OFF_B_HI + n * RB + k] = hw;
            sm[OFF_B_LO + n * RB + k] = __float2bfloat16_rn(lw);
        }
        __syncthreads();

        const int aOffC[3] = { OFF_A_HI, OFF_A_HI, OFF_A_LO };
        const int bOffC[3] = { OFF_B_HI, OFF_B_LO, OFF_B_HI };
        #pragma unroll
        for (int c = 0; c < 3; c++) {
            uint32_t aBase = sbase + (uint32_t)(aOffC[c] + aRow * RA + aColB) * 2;
            uint32_t bBase = sbase + (uint32_t)(bOffC[c] + bRow * RB + bColB) * 2;
            #pragma unroll
            for (int ks = 0; ks < 4; ks++) {
                uint32_t a[4], b[2][4];
                ldsm_x4(a[0], a[1], a[2], a[3],
                        aBase + (uint32_t)(ks * 16) * 2);
                #pragma unroll
                for (int nb = 0; nb < 2; nb++)
                    ldsm_x4(b[nb][0], b[nb][1], b[nb][2], b[nb][3],
                            bBase + (uint32_t)(nb * 16 * RB + ks * 16) * 2);
                #pragma unroll
                for (int ni = 0; ni < 4; ni++)
                    mma_bf16(acc[ni], a,
                             b[ni >> 1][(ni & 1) * 2],
                             b[ni >> 1][(ni & 1) * 2 + 1]);
            }
        }
    }

    // Epilogue: bias (+tanh)
    #pragma unroll
    for (int ni = 0; ni < 4; ni++) {
        int col = n0 + ni * 8 + (lane & 3) * 2;
        float b0 = __ldg(bias + col);
        float b1 = __ldg(bias + col + 1);
        int r0 = rowBase + m0 + (lane >> 2);
        #pragma unroll
        for (int h = 0; h < 2; h++) {
            int r = r0 + h * 8;
            if (r >= N_NODES) continue;
            float v0 = acc[ni][h * 2]     + b0;
            float v1 = acc[ni][h * 2 + 1] + b1;
            if (doTanh) {
                asm("tanh.approx.f32 %0, %0;" : "+f"(v0));
                asm("tanh.approx.f32 %0, %0;" : "+f"(v1));
            }
            *(float2*)(out + (size_t)r * 64 + col) = make_float2(v0, v1);
        }
    }
}

// ---------------------------------------------------------------------------
// Launcher (R11 structure: scatter -> PDL gemm, per layer)
// ---------------------------------------------------------------------------
extern "C" void kernel_launch(void* const* d_in, const int* in_sizes, int n_in,
                              void* d_out, int out_size)
{
    const float* x      = (const float*)d_in[0];
    const int*   eidx   = (const int*)  d_in[1];
    const float* ew     = (const float*)d_in[2];
    const float* W_rel  = (const float*)d_in[3];
    const float* b_rel  = (const float*)d_in[4];
    const float* W_root = (const float*)d_in[5];
    float* out = (float*)d_out;

    const int* src = eidx;
    const int* dst = eidx + N_EDGES;

    float *pA, *pB, *pAgg;
    cudaGetSymbolAddress((void**)&pA,   g_bufA);
    cudaGetSymbolAddress((void**)&pB,   g_bufB);
    cudaGetSymbolAddress((void**)&pAgg, g_agg);

    static bool attrSet = false;
    if (!attrSet) {
        cudaFuncSetAttribute(gemm_tc_kernel,
                             cudaFuncAttributeMaxDynamicSharedMemorySize,
                             SMEM_BYTES);
        attrSet = true;
    }

    const int n4 = N_NODES * (DIM / 4);
    const int zeroBlocks    = (n4 + 255) / 256;
    const int scatterBlocks = N_EDGES / (4 * 16);      // 12500
    const int gemmBlocks    = (N_NODES + 63) / 64;     // 782

    zero_kernel<<<zeroBlocks, 256>>>((float4*)pAgg, n4);

    const float* hprev = x;
    for (int layer = 0; layer < NLAYERS; layer++) {
        float* hnext = (layer == NLAYERS - 1) ? out : ((layer == 0) ? pA : pB);

        scatter_hybrid_kernel<<<scatterBlocks, 128>>>(
            (const float4*)hprev, src, dst, ew, pAgg);

        // GEMM as PDL secondary: stage 0 overlaps the scatter tail.
        {
            cudaLaunchConfig_t cfg = {};
            cfg.gridDim  = dim3(gemmBlocks);
            cfg.blockDim = dim3(256);
            cfg.dynamicSmemBytes = SMEM_BYTES;
            cfg.stream = 0;
            cudaLaunchAttribute at[1];
            at[0].id = cudaLaunchAttributeProgrammaticStreamSerialization;
            at[0].val.programmaticStreamSerializationAllowed = 1;
            cfg.attrs = at;
            cfg.numAttrs = 1;

            const float* Wr = W_root + (size_t)layer * DIM * DIM;
            const float* We = W_rel  + (size_t)layer * DIM * DIM;
            const float* bs = b_rel  + (size_t)layer * DIM;
            int doTanh = (layer == NLAYERS - 1) ? 1 : 0;
            int doZero = (layer == NLAYERS - 1) ? 0 : 1;
            cudaLaunchKernelEx(&cfg, gemm_tc_kernel,
                               hprev, pAgg, Wr, We, bs, hnext, doTanh, doZero);
        }

        hprev = hnext;
    }
}

// round 16
// speedup vs baseline: 1.1198x; 1.0703x over previous
#include <cuda_runtime.h>
#include <cuda_bf16.h>
#include <cstdint>

#define N_NODES 50000
#define N_EDGES 800000
#define DIM     64
#define NLAYERS 3

// A/B row strides in bf16 elems (64 data + 8 pad -> conflict-free LDSM)
#define RA 72
#define RB 72
// SMEM layout (bf16 elems): one A tile (128 rows), two W tiles (hi/lo each)
#define OFF_A_HI  0
#define OFF_A_LO  (128 * RA)
#define OFF_B0_HI (2 * 128 * RA)
#define OFF_B0_LO (2 * 128 * RA + 64 * RB)
#define OFF_B1_HI (2 * 128 * RA + 2 * 64 * RB)
#define OFF_B1_LO (2 * 128 * RA + 3 * 64 * RB)
#define SMEM_ELEMS (2 * 128 * RA + 4 * 64 * RB)
#define SMEM_BYTES (SMEM_ELEMS * 2)        // 73,728 B

// Scratch (no cudaMalloc allowed).
__device__ float g_bufA[N_NODES * DIM];
__device__ float g_bufB[N_NODES * DIM];
__device__ float g_agg [N_NODES * DIM];

// ---------------------------------------------------------------------------
__global__ void zero_kernel(float4* __restrict__ p, int n4) {
    int i = blockIdx.x * blockDim.x + threadIdx.x;
    if (i < n4) p[i] = make_float4(0.f, 0.f, 0.f, 0.f);
}

// ---------------------------------------------------------------------------
// HYBRID scatter (R11, at the L2 throughput wall — unchanged).
// ---------------------------------------------------------------------------
__global__ __launch_bounds__(128) void scatter_hybrid_kernel(
    const float4* __restrict__ h,
    const int*    __restrict__ src,
    const int*    __restrict__ dst,
    const float*  __restrict__ ew,
    float*        __restrict__ agg)
{
    __shared__ float4 buf[4][8][16];

    const int warp = threadIdx.x >> 5;
    const int lane = threadIdx.x & 31;
    const int sub  = lane >> 4;
    const int l16  = lane & 15;

    const long eBase = ((long)blockIdx.x * 4 + warp) * 16;

    int   myS = 0, myD = 0;
    float myW = 0.f;
    if (lane < 16) {
        myS = __ldg(src + eBase + lane);
        myD = __ldg(dst + eBase + lane);
        myW = __ldg(ew  + eBase + lane);
    }

    #pragma unroll
    for (int it = 0; it < 4; it++) {
        int   k = it * 2 + sub;
        int   s = __shfl_sync(0xffffffffu, myS, k);
        float w = __shfl_sync(0xffffffffu, myW, k);
        float4 v = __ldg(h + (size_t)s * 16 + l16);
        v.x *= w; v.y *= w; v.z *= w; v.w *= w;
        buf[warp][k][l16] = v;
    }
    __syncwarp();
    asm volatile("fence.proxy.async.shared::cta;" ::: "memory");

    if (lane < 8) {
        uint32_t sp = (uint32_t)__cvta_generic_to_shared(&buf[warp][lane][0]);
        float* gp = agg + (size_t)myD * 64;
        asm volatile(
            "cp.reduce.async.bulk.global.shared::cta.bulk_group.add.f32 "
            "[%0], [%1], %2;"
            :: "l"(gp), "r"(sp), "n"(256) : "memory");
        asm volatile("cp.async.bulk.commit_group;" ::: "memory");
    }

    #pragma unroll
    for (int it = 0; it < 4; it++) {
        int   k = 8 + it * 2 + sub;
        int   s = __shfl_sync(0xffffffffu, myS, k);
        int   d = __shfl_sync(0xffffffffu, myD, k);
        float w = __shfl_sync(0xffffffffu, myW, k);
        float4 v = __ldg(h + (size_t)s * 16 + l16);
        float4* p = (float4*)agg + (size_t)d * 16 + l16;
        asm volatile("red.global.add.v4.f32 [%0], {%1,%2,%3,%4};"
                     :: "l"(p), "f"(v.x * w), "f"(v.y * w),
                        "f"(v.z * w), "f"(v.w * w)
                     : "memory");
    }

    if (lane < 8)
        asm volatile("cp.async.bulk.wait_group 0;" ::: "memory");
}

// ---------------------------------------------------------------------------
// TC dual GEMM, bf16-split, fp32 accum; 128-row tile, 256 thr.
// Pipelined: W tiles both staged pre-sync; AGG prefetched into registers
// (8 float4/thread = full tile) under stage-0 compute; A buffer reused.
// ---------------------------------------------------------------------------
__device__ __forceinline__ void ldsm_x4(uint32_t& r0, uint32_t& r1,
                                        uint32_t& r2, uint32_t& r3,
                                        uint32_t addr) {
    asm volatile("ldmatrix.sync.aligned.m8n8.x4.shared.b16 {%0,%1,%2,%3}, [%4];"
                 : "=r"(r0), "=r"(r1), "=r"(r2), "=r"(r3) : "r"(addr));
}

__device__ __forceinline__ void mma_bf16(float* d, const uint32_t* a,
                                         uint32_t b0, uint32_t b1) {
    asm volatile(
        "mma.sync.aligned.m16n8k16.row.col.f32.bf16.bf16.f32 "
        "{%0,%1,%2,%3}, {%4,%5,%6,%7}, {%8,%9}, {%0,%1,%2,%3};"
        : "+f"(d[0]), "+f"(d[1]), "+f"(d[2]), "+f"(d[3])
        : "r"(a[0]), "r"(a[1]), "r"(a[2]), "r"(a[3]), "r"(b0), "r"(b1));
}

__device__ __forceinline__ void split2(float a, float b,
                                       __nv_bfloat162& h, __nv_bfloat162& l) {
    __nv_bfloat16 ha = __float2bfloat16_rn(a);
    __nv_bfloat16 hb = __float2bfloat16_rn(b);
    float la = a - __bfloat162float(ha);
    float lb = b - __bfloat162float(hb);
    h = __halves2bfloat162(ha, hb);
    l = __halves2bfloat162(__float2bfloat16_rn(la), __float2bfloat16_rn(lb));
}

// One stage of 3-combo (hi*hi, hi*lo, lo*hi) K=64 MMAs.
__device__ __forceinline__ void compute_stage(
    float acc[2][4][4], uint32_t sbase, int offBHi, int offBLo,
    int aRow, int aColB, int bRow, int bColB)
{
    const int aOffC[3] = { OFF_A_HI, OFF_A_HI, OFF_A_LO };
    const int bOffC[3] = { offBHi, offBLo, offBHi };
    #pragma unroll
    for (int c = 0; c < 3; c++) {
        uint32_t aBase = sbase + (uint32_t)(aOffC[c] + aRow * RA + aColB) * 2;
        uint32_t bBase = sbase + (uint32_t)(bOffC[c] + bRow * RB + bColB) * 2;
        #pragma unroll
        for (int ks = 0; ks < 4; ks++) {
            uint32_t a[2][4], b[2][4];
            #pragma unroll
            for (int mi = 0; mi < 2; mi++)
                ldsm_x4(a[mi][0], a[mi][1], a[mi][2], a[mi][3],
                        aBase + (uint32_t)(mi * 16 * RA + ks * 16) * 2);
            #pragma unroll
            for (int nb = 0; nb < 2; nb++)
                ldsm_x4(b[nb][0], b[nb][1], b[nb][2], b[nb][3],
                        bBase + (uint32_t)(nb * 16 * RB + ks * 16) * 2);
            #pragma unroll
            for (int mi = 0; mi < 2; mi++)
                #pragma unroll
                for (int ni = 0; ni < 4; ni++)
                    mma_bf16(acc[mi][ni], a[mi],
                             b[ni >> 1][(ni & 1) * 2],
                             b[ni >> 1][(ni & 1) * 2 + 1]);
        }
    }
}

__global__ __launch_bounds__(256) void gemm_tc_kernel(
    const float* __restrict__ H,
    float*                    AGG,     // no restrict: loaded then zeroed
    const float* __restrict__ Wroot,   // [64][64]
    const float* __restrict__ Wrel,    // [64][64]
    const float* __restrict__ bias,    // [64]
    float*       __restrict__ out,
    int doTanh, int doZero)
{
    extern __shared__ __nv_bfloat16 sm[];
    uint32_t sbase;
    asm("{.reg .u64 t; cvta.to.shared.u64 t, %1; cvt.u32.u64 %0, t;}"
        : "=r"(sbase) : "l"(sm));

    const int tid     = threadIdx.x;
    const int lane    = tid & 31;
    const int warp    = tid >> 5;
    const int wm      = warp >> 1;
    const int wn      = warp & 1;
    const int rowBase = blockIdx.x * 128;

    float acc[2][4][4];
    #pragma unroll
    for (int mi = 0; mi < 2; mi++)
        #pragma unroll
        for (int ni = 0; ni < 4; ni++)
            #pragma unroll
            for (int k = 0; k < 4; k++) acc[mi][ni][k] = 0.f;

    const int m0 = wm * 32;
    const int n0 = wn * 32;
    const int aRow  = m0 + (lane & 15);
    const int aColB = (lane >> 4) * 8;
    const int bRow  = n0 + (lane & 7) + ((lane >> 4) * 8);
    const int bColB = ((lane >> 3) & 1) * 8;

    // ---- Pre-sync staging: H tile + BOTH W tiles ----
    #pragma unroll
    for (int i = 0; i < 8; i++) {
        int q   = tid + i * 256;
        int row = q >> 4;
        int c4  = (q & 15) * 4;
        int gr  = rowBase + row;
        float4 v = make_float4(0.f, 0.f, 0.f, 0.f);
        if (gr < N_NODES) v = *(const float4*)(H + (size_t)gr * 64 + c4);
        __nv_bfloat162 h0, l0, h1, l1;
        split2(v.x, v.y, h0, l0);
        split2(v.z, v.w, h1, l1);
        int base = row * RA + c4;
        *(__nv_bfloat162*)&sm[OFF_A_HI + base]     = h0;
        *(__nv_bfloat162*)&sm[OFF_A_HI + base + 2] = h1;
        *(__nv_bfloat162*)&sm[OFF_A_LO + base]     = l0;
        *(__nv_bfloat162*)&sm[OFF_A_LO + base + 2] = l1;
    }
    #pragma unroll
    for (int i = 0; i < 16; i++) {
        int q = tid + i * 256;
        int k = q >> 6;
        int n = q & 63;
        float w0 = __ldg(Wroot + k * 64 + n);
        float w1 = __ldg(Wrel  + k * 64 + n);
        __nv_bfloat16 h0 = __float2bfloat16_rn(w0);
        __nv_bfloat16 h1 = __float2bfloat16_rn(w1);
        sm[OFF_B0_HI + n * RB + k] = h0;
        sm[OFF_B0_LO + n * RB + k] =
            __float2bfloat16_rn(w0 - __bfloat162float(h0));
        sm[OFF_B1_HI + n * RB + k] = h1;
        sm[OFF_B1_LO + n * RB + k] =
            __float2bfloat16_rn(w1 - __bfloat162float(h1));
    }
    __syncthreads();

    // ---- Wait for scatter, then PREFETCH FULL AGG tile into registers ----
    // 128 rows x 16 float4 = 2048 float4; 256 threads x 8 float4 each.
    // Thread covers row = tid>>1, float4 indices half*8 .. half*8+7
    // (float columns half*32 .. half*32+31), half = tid&1.
    cudaGridDependencySynchronize();
    const int ldRow = tid >> 1;                // 0..127
    const int half  = tid & 1;                 // 0/1
    const int ldGr  = rowBase + ldRow;
    const bool ldOk = (ldGr < N_NODES);
    float4 av[8];
    {
        const float4* base = (const float4*)(AGG + (size_t)ldGr * 64) + half * 8;
        #pragma unroll
        for (int i = 0; i < 8; i++)
            av[i] = ldOk ? __ldg(base + i)
                         : make_float4(0.f, 0.f, 0.f, 0.f);
    }

    // ---- Stage-0 compute (H @ Wroot) hides the AGG loads ----
    compute_stage(acc, sbase, OFF_B0_HI, OFF_B0_LO, aRow, aColB, bRow, bColB);
    __syncthreads();   // all warps done reading H from the A buffer

    // ---- Convert prefetched AGG -> A buffer; zero AGG ----
    {
        #pragma unroll
        for (int i = 0; i < 8; i++) {
            int c4 = half * 32 + i * 4;        // float column
            __nv_bfloat162 h0, l0, h1, l1;
            split2(av[i].x, av[i].y, h0, l0);
            split2(av[i].z, av[i].w, h1, l1);
            int base = ldRow * RA + c4;
            *(__nv_bfloat162*)&sm[OFF_A_HI + base]     = h0;
            *(__nv_bfloat162*)&sm[OFF_A_HI + base + 2] = h1;
            *(__nv_bfloat162*)&sm[OFF_A_LO + base]     = l0;
            *(__nv_bfloat162*)&sm[OFF_A_LO + base + 2] = l1;
            if (doZero && ldOk)
                *((float4*)(AGG + (size_t)ldGr * 64) + half * 8 + i) =
                    make_float4(0.f, 0.f, 0.f, 0.f);
        }
    }
    __syncthreads();

    // ---- Stage-1 compute (AGG @ Wrel) ----
    compute_stage(acc, sbase, OFF_B1_HI, OFF_B1_LO, aRow, aColB, bRow, bColB);

    // ---- Epilogue: bias (+tanh) ----
    #pragma unroll
    for (int mi = 0; mi < 2; mi++) {
        #pragma unroll
        for (int ni = 0; ni < 4; ni++) {
            int col = n0 + ni * 8 + (lane & 3) * 2;
            float b0 = __ldg(bias + col);
            float b1 = __ldg(bias + col + 1);
            int r0 = rowBase + m0 + mi * 16 + (lane >> 2);
            #pragma unroll
            for (int h = 0; h < 2; h++) {
                int r = r0 + h * 8;
                if (r >= N_NODES) continue;
                float v0 = acc[mi][ni][h * 2]     + b0;
                float v1 = acc[mi][ni][h * 2 + 1] + b1;
                if (doTanh) {
                    asm("tanh.approx.f32 %0, %0;" : "+f"(v0));
                    asm("tanh.approx.f32 %0, %0;" : "+f"(v1));
                }
                *(float2*)(out + (size_t)r * 64 + col) = make_float2(v0, v1);
            }
        }
    }
}

// ---------------------------------------------------------------------------
// Launcher (R11 structure: scatter -> PDL gemm, per layer)
// ---------------------------------------------------------------------------
extern "C" void kernel_launch(void* const* d_in, const int* in_sizes, int n_in,
                              void* d_out, int out_size)
{
    const float* x      = (const float*)d_in[0];
    const int*   eidx   = (const int*)  d_in[1];
    const float* ew     = (const float*)d_in[2];
    const float* W_rel  = (const float*)d_in[3];
    const float* b_rel  = (const float*)d_in[4];
    const float* W_root = (const float*)d_in[5];
    float* out = (float*)d_out;

    const int* src = eidx;
    const int* dst = eidx + N_EDGES;

    float *pA, *pB, *pAgg;
    cudaGetSymbolAddress((void**)&pA,   g_bufA);
    cudaGetSymbolAddress((void**)&pB,   g_bufB);
    cudaGetSymbolAddress((void**)&pAgg, g_agg);

    static bool attrSet = false;
    if (!attrSet) {
        cudaFuncSetAttribute(gemm_tc_kernel,
                             cudaFuncAttributeMaxDynamicSharedMemorySize,
                             SMEM_BYTES);
        attrSet = true;
    }

    const int n4 = N_NODES * (DIM / 4);
    const int zeroBlocks    = (n4 + 255) / 256;
    const int scatterBlocks = N_EDGES / (4 * 16);      // 12500
    const int gemmBlocks    = (N_NODES + 127) / 128;   // 391

    zero_kernel<<<zeroBlocks, 256>>>((float4*)pAgg, n4);

    const float* hprev = x;
    for (int layer = 0; layer < NLAYERS; layer++) {
        float* hnext = (layer == NLAYERS - 1) ? out : ((layer == 0) ? pA : pB);

        scatter_hybrid_kernel<<<scatterBlocks, 128>>>(
            (const float4*)hprev, src, dst, ew, pAgg);

        // GEMM as PDL secondary: pre-sync staging overlaps the scatter tail.
        {
            cudaLaunchConfig_t cfg = {};
            cfg.gridDim  = dim3(gemmBlocks);
            cfg.blockDim = dim3(256);
            cfg.dynamicSmemBytes = SMEM_BYTES;
            cfg.stream = 0;
            cudaLaunchAttribute at[1];
            at[0].id = cudaLaunchAttributeProgrammaticStreamSerialization;
            at[0].val.programmaticStreamSerializationAllowed = 1;
            cfg.attrs = at;
            cfg.numAttrs = 1;

            const float* Wr = W_root + (size_t)layer * DIM * DIM;
            const float* We = W_rel  + (size_t)layer * DIM * DIM;
            const float* bs = b_rel  + (size_t)layer * DIM;
            int doTanh = (layer == NLAYERS - 1) ? 1 : 0;
            int doZero = (layer == NLAYERS - 1) ? 0 : 1;
            cudaLaunchKernelEx(&cfg, gemm_tc_kernel,
                               hprev, pAgg, Wr, We, bs, hnext, doTanh, doZero);
        }

        hprev = hnext;
    }
}

// round 17
// speedup vs baseline: 1.1204x; 1.0006x over previous
#include <cuda_runtime.h>
#include <cuda_bf16.h>
#include <cstdint>

#define N_NODES 50000
#define N_EDGES 800000
#define DIM     64
#define NLAYERS 3

// A/B row strides in bf16 elems (64 data + 8 pad -> conflict-free LDSM)
#define RA 72
#define RB 72
// SMEM layout (bf16 elems): one A tile (128 rows), two W tiles (hi/lo each)
#define OFF_A_HI  0
#define OFF_A_LO  (128 * RA)
#define OFF_B0_HI (2 * 128 * RA)
#define OFF_B0_LO (2 * 128 * RA + 64 * RB)
#define OFF_B1_HI (2 * 128 * RA + 2 * 64 * RB)
#define OFF_B1_LO (2 * 128 * RA + 3 * 64 * RB)
#define SMEM_ELEMS (2 * 128 * RA + 4 * 64 * RB)
#define SMEM_BYTES (SMEM_ELEMS * 2)        // 73,728 B

// Scratch (no cudaMalloc allowed). g_agg is zero-initialized at module load;
// every layer's GEMM re-zeroes it after consumption, so it is ALWAYS zero at
// kernel_launch entry (invariant maintained across graph replays).
__device__ float g_bufA[N_NODES * DIM];
__device__ float g_bufB[N_NODES * DIM];
__device__ float g_agg [N_NODES * DIM];

// ---------------------------------------------------------------------------
// HYBRID scatter (R11 core, at the L2 throughput wall). PDL-aware:
// edge-key loads (independent of the previous GEMM's output) run pre-sync;
// cudaGridDependencySynchronize() gates the h-gather and agg-reduce.
// ---------------------------------------------------------------------------
__global__ __launch_bounds__(128) void scatter_hybrid_kernel(
    const float4* __restrict__ h,
    const int*    __restrict__ src,
    const int*    __restrict__ dst,
    const float*  __restrict__ ew,
    float*        __restrict__ agg)
{
    __shared__ float4 buf[4][8][16];

    const int warp = threadIdx.x >> 5;
    const int lane = threadIdx.x & 31;
    const int sub  = lane >> 4;
    const int l16  = lane & 15;

    const long eBase = ((long)blockIdx.x * 4 + warp) * 16;

    // Pre-sync: edge keys (don't depend on h or agg)
    int   myS = 0, myD = 0;
    float myW = 0.f;
    if (lane < 16) {
        myS = __ldg(src + eBase + lane);
        myD = __ldg(dst + eBase + lane);
        myW = __ldg(ew  + eBase + lane);
    }

    // Gate: h (previous GEMM output) and agg (zeroed by previous GEMM)
    cudaGridDependencySynchronize();

    #pragma unroll
    for (int it = 0; it < 4; it++) {
        int   k = it * 2 + sub;
        int   s = __shfl_sync(0xffffffffu, myS, k);
        float w = __shfl_sync(0xffffffffu, myW, k);
        float4 v = __ldg(h + (size_t)s * 16 + l16);
        v.x *= w; v.y *= w; v.z *= w; v.w *= w;
        buf[warp][k][l16] = v;
    }
    __syncwarp();
    asm volatile("fence.proxy.async.shared::cta;" ::: "memory");

    if (lane < 8) {
        uint32_t sp = (uint32_t)__cvta_generic_to_shared(&buf[warp][lane][0]);
        float* gp = agg + (size_t)myD * 64;
        asm volatile(
            "cp.reduce.async.bulk.global.shared::cta.bulk_group.add.f32 "
            "[%0], [%1], %2;"
            :: "l"(gp), "r"(sp), "n"(256) : "memory");
        asm volatile("cp.async.bulk.commit_group;" ::: "memory");
    }

    #pragma unroll
    for (int it = 0; it < 4; it++) {
        int   k = 8 + it * 2 + sub;
        int   s = __shfl_sync(0xffffffffu, myS, k);
        int   d = __shfl_sync(0xffffffffu, myD, k);
        float w = __shfl_sync(0xffffffffu, myW, k);
        float4 v = __ldg(h + (size_t)s * 16 + l16);
        float4* p = (float4*)agg + (size_t)d * 16 + l16;
        asm volatile("red.global.add.v4.f32 [%0], {%1,%2,%3,%4};"
                     :: "l"(p), "f"(v.x * w), "f"(v.y * w),
                        "f"(v.z * w), "f"(v.w * w)
                     : "memory");
    }

    if (lane < 8)
        asm volatile("cp.async.bulk.wait_group 0;" ::: "memory");
}

// ---------------------------------------------------------------------------
// TC dual GEMM, bf16-split, fp32 accum; 128-row tile, 256 thr.
// Pipelined: W tiles both staged pre-sync; AGG prefetched into registers
// (8 float4/thread = full tile) under stage-0 compute; A buffer reused.
// Zeroes AGG after consumption (every layer) to maintain the entry invariant.
// ---------------------------------------------------------------------------
__device__ __forceinline__ void ldsm_x4(uint32_t& r0, uint32_t& r1,
                                        uint32_t& r2, uint32_t& r3,
                                        uint32_t addr) {
    asm volatile("ldmatrix.sync.aligned.m8n8.x4.shared.b16 {%0,%1,%2,%3}, [%4];"
                 : "=r"(r0), "=r"(r1), "=r"(r2), "=r"(r3) : "r"(addr));
}

__device__ __forceinline__ void mma_bf16(float* d, const uint32_t* a,
                                         uint32_t b0, uint32_t b1) {
    asm volatile(
        "mma.sync.aligned.m16n8k16.row.col.f32.bf16.bf16.f32 "
        "{%0,%1,%2,%3}, {%4,%5,%6,%7}, {%8,%9}, {%0,%1,%2,%3};"
        : "+f"(d[0]), "+f"(d[1]), "+f"(d[2]), "+f"(d[3])
        : "r"(a[0]), "r"(a[1]), "r"(a[2]), "r"(a[3]), "r"(b0), "r"(b1));
}

__device__ __forceinline__ void split2(float a, float b,
                                       __nv_bfloat162& h, __nv_bfloat162& l) {
    __nv_bfloat16 ha = __float2bfloat16_rn(a);
    __nv_bfloat16 hb = __float2bfloat16_rn(b);
    float la = a - __bfloat162float(ha);
    float lb = b - __bfloat162float(hb);
    h = __halves2bfloat162(ha, hb);
    l = __halves2bfloat162(__float2bfloat16_rn(la), __float2bfloat16_rn(lb));
}

// One stage of 3-combo (hi*hi, hi*lo, lo*hi) K=64 MMAs.
__device__ __forceinline__ void compute_stage(
    float acc[2][4][4], uint32_t sbase, int offBHi, int offBLo,
    int aRow, int aColB, int bRow, int bColB)
{
    const int aOffC[3] = { OFF_A_HI, OFF_A_HI, OFF_A_LO };
    const int bOffC[3] = { offBHi, offBLo, offBHi };
    #pragma unroll
    for (int c = 0; c < 3; c++) {
        uint32_t aBase = sbase + (uint32_t)(aOffC[c] + aRow * RA + aColB) * 2;
        uint32_t bBase = sbase + (uint32_t)(bOffC[c] + bRow * RB + bColB) * 2;
        #pragma unroll
        for (int ks = 0; ks < 4; ks++) {
            uint32_t a[2][4], b[2][4];
            #pragma unroll
            for (int mi = 0; mi < 2; mi++)
                ldsm_x4(a[mi][0], a[mi][1], a[mi][2], a[mi][3],
                        aBase + (uint32_t)(mi * 16 * RA + ks * 16) * 2);
            #pragma unroll
            for (int nb = 0; nb < 2; nb++)
                ldsm_x4(b[nb][0], b[nb][1], b[nb][2], b[nb][3],
                        bBase + (uint32_t)(nb * 16 * RB + ks * 16) * 2);
            #pragma unroll
            for (int mi = 0; mi < 2; mi++)
                #pragma unroll
                for (int ni = 0; ni < 4; ni++)
                    mma_bf16(acc[mi][ni], a[mi],
                             b[ni >> 1][(ni & 1) * 2],
                             b[ni >> 1][(ni & 1) * 2 + 1]);
        }
    }
}

__global__ __launch_bounds__(256) void gemm_tc_kernel(
    const float* __restrict__ H,
    float*                    AGG,     // no restrict: loaded then zeroed
    const float* __restrict__ Wroot,   // [64][64]
    const float* __restrict__ Wrel,    // [64][64]
    const float* __restrict__ bias,    // [64]
    float*       __restrict__ out,
    int doTanh)
{
    extern __shared__ __nv_bfloat16 sm[];
    uint32_t sbase;
    asm("{.reg .u64 t; cvta.to.shared.u64 t, %1; cvt.u32.u64 %0, t;}"
        : "=r"(sbase) : "l"(sm));

    const int tid     = threadIdx.x;
    const int lane    = tid & 31;
    const int warp    = tid >> 5;
    const int wm      = warp >> 1;
    const int wn      = warp & 1;
    const int rowBase = blockIdx.x * 128;

    float acc[2][4][4];
    #pragma unroll
    for (int mi = 0; mi < 2; mi++)
        #pragma unroll
        for (int ni = 0; ni < 4; ni++)
            #pragma unroll
            for (int k = 0; k < 4; k++) acc[mi][ni][k] = 0.f;

    const int m0 = wm * 32;
    const int n0 = wn * 32;
    const int aRow  = m0 + (lane & 15);
    const int aColB = (lane >> 4) * 8;
    const int bRow  = n0 + (lane & 7) + ((lane >> 4) * 8);
    const int bColB = ((lane >> 3) & 1) * 8;

    // ---- Pre-sync staging: H tile + BOTH W tiles ----
    #pragma unroll
    for (int i = 0; i < 8; i++) {
        int q   = tid + i * 256;
        int row = q >> 4;
        int c4  = (q & 15) * 4;
        int gr  = rowBase + row;
        float4 v = make_float4(0.f, 0.f, 0.f, 0.f);
        if (gr < N_NODES) v = *(const float4*)(H + (size_t)gr * 64 + c4);
        __nv_bfloat162 h0, l0, h1, l1;
        split2(v.x, v.y, h0, l0);
        split2(v.z, v.w, h1, l1);
        int base = row * RA + c4;
        *(__nv_bfloat162*)&sm[OFF_A_HI + base]     = h0;
        *(__nv_bfloat162*)&sm[OFF_A_HI + base + 2] = h1;
        *(__nv_bfloat162*)&sm[OFF_A_LO + base]     = l0;
        *(__nv_bfloat162*)&sm[OFF_A_LO + base + 2] = l1;
    }
    #pragma unroll
    for (int i = 0; i < 16; i++) {
        int q = tid + i * 256;
        int k = q >> 6;
        int n = q & 63;
        float w0 = __ldg(Wroot + k * 64 + n);
        float w1 = __ldg(Wrel  + k * 64 + n);
        __nv_bfloat16 h0 = __float2bfloat16_rn(w0);
        __nv_bfloat16 h1 = __float2bfloat16_rn(w1);
        sm[OFF_B0_HI + n * RB + k] = h0;
        sm[OFF_B0_LO + n * RB + k] =
            __float2bfloat16_rn(w0 - __bfloat162float(h0));
        sm[OFF_B1_HI + n * RB + k] = h1;
        sm[OFF_B1_LO + n * RB + k] =
            __float2bfloat16_rn(w1 - __bfloat162float(h1));
    }
    __syncthreads();

    // ---- Wait for scatter, then PREFETCH FULL AGG tile into registers ----
    cudaGridDependencySynchronize();
    const int ldRow = tid >> 1;                // 0..127
    const int half  = tid & 1;                 // 0/1
    const int ldGr  = rowBase + ldRow;
    const bool ldOk = (ldGr < N_NODES);
    float4 av[8];
    {
        const float4* base = (const float4*)(AGG + (size_t)ldGr * 64) + half * 8;
        #pragma unroll
        for (int i = 0; i < 8; i++)
            av[i] = ldOk ? __ldg(base + i)
                         : make_float4(0.f, 0.f, 0.f, 0.f);
    }

    // ---- Stage-0 compute (H @ Wroot) hides the AGG loads ----
    compute_stage(acc, sbase, OFF_B0_HI, OFF_B0_LO, aRow, aColB, bRow, bColB);
    __syncthreads();   // all warps done reading H from the A buffer

    // ---- Convert prefetched AGG -> A buffer; zero AGG (every layer) ----
    {
        #pragma unroll
        for (int i = 0; i < 8; i++) {
            int c4 = half * 32 + i * 4;        // float column
            __nv_bfloat162 h0, l0, h1, l1;
            split2(av[i].x, av[i].y, h0, l0);
            split2(av[i].z, av[i].w, h1, l1);
            int base = ldRow * RA + c4;
            *(__nv_bfloat162*)&sm[OFF_A_HI + base]     = h0;
            *(__nv_bfloat162*)&sm[OFF_A_HI + base + 2] = h1;
            *(__nv_bfloat162*)&sm[OFF_A_LO + base]     = l0;
            *(__nv_bfloat162*)&sm[OFF_A_LO + base + 2] = l1;
            if (ldOk)
                *((float4*)(AGG + (size_t)ldGr * 64) + half * 8 + i) =
                    make_float4(0.f, 0.f, 0.f, 0.f);
        }
    }
    __syncthreads();

    // ---- Stage-1 compute (AGG @ Wrel) ----
    compute_stage(acc, sbase, OFF_B1_HI, OFF_B1_LO, aRow, aColB, bRow, bColB);

    // ---- Epilogue: bias (+tanh) ----
    #pragma unroll
    for (int mi = 0; mi < 2; mi++) {
        #pragma unroll
        for (int ni = 0; ni < 4; ni++) {
            int col = n0 + ni * 8 + (lane & 3) * 2;
            float b0 = __ldg(bias + col);
            float b1 = __ldg(bias + col + 1);
            int r0 = rowBase + m0 + mi * 16 + (lane >> 2);
            #pragma unroll
            for (int h = 0; h < 2; h++) {
                int r = r0 + h * 8;
                if (r >= N_NODES) continue;
                float v0 = acc[mi][ni][h * 2]     + b0;
                float v1 = acc[mi][ni][h * 2 + 1] + b1;
                if (doTanh) {
                    asm("tanh.approx.f32 %0, %0;" : "+f"(v0));
                    asm("tanh.approx.f32 %0, %0;" : "+f"(v1));
                }
                *(float2*)(out + (size_t)r * 64 + col) = make_float2(v0, v1);
            }
        }
    }
}

// ---------------------------------------------------------------------------
// Launcher: (scatter[PDL], gemm[PDL]) x3 — no zero kernel (AGG invariant).
// ---------------------------------------------------------------------------
extern "C" void kernel_launch(void* const* d_in, const int* in_sizes, int n_in,
                              void* d_out, int out_size)
{
    const float* x      = (const float*)d_in[0];
    const int*   eidx   = (const int*)  d_in[1];
    const float* ew     = (const float*)d_in[2];
    const float* W_rel  = (const float*)d_in[3];
    const float* b_rel  = (const float*)d_in[4];
    const float* W_root = (const float*)d_in[5];
    float* out = (float*)d_out;

    const int* src = eidx;
    const int* dst = eidx + N_EDGES;

    float *pA, *pB, *pAgg;
    cudaGetSymbolAddress((void**)&pA,   g_bufA);
    cudaGetSymbolAddress((void**)&pB,   g_bufB);
    cudaGetSymbolAddress((void**)&pAgg, g_agg);

    static bool attrSet = false;
    if (!attrSet) {
        cudaFuncSetAttribute(gemm_tc_kernel,
                             cudaFuncAttributeMaxDynamicSharedMemorySize,
                             SMEM_BYTES);
        attrSet = true;
    }

    const int scatterBlocks = N_EDGES / (4 * 16);      // 12500
    const int gemmBlocks    = (N_NODES + 127) / 128;   // 391

    cudaLaunchAttribute pdlAttr[1];
    pdlAttr[0].id = cudaLaunchAttributeProgrammaticStreamSerialization;
    pdlAttr[0].val.programmaticStreamSerializationAllowed = 1;

    const float* hprev = x;
    for (int layer = 0; layer < NLAYERS; layer++) {
        float* hnext = (layer == NLAYERS - 1) ? out : ((layer == 0) ? pA : pB);

        // Scatter as PDL secondary: key loads overlap previous GEMM's tail.
        {
            cudaLaunchConfig_t cfg = {};
            cfg.gridDim  = dim3(scatterBlocks);
            cfg.blockDim = dim3(128);
            cfg.dynamicSmemBytes = 0;
            cfg.stream = 0;
            cfg.attrs = pdlAttr;
            cfg.numAttrs = 1;
            cudaLaunchKernelEx(&cfg, scatter_hybrid_kernel,
                               (const float4*)hprev, src, dst, ew, pAgg);
        }

        // GEMM as PDL secondary: H/W staging overlaps the scatter tail.
        {
            cudaLaunchConfig_t cfg = {};
            cfg.gridDim  = dim3(gemmBlocks);
            cfg.blockDim = dim3(256);
            cfg.dynamicSmemBytes = SMEM_BYTES;
            cfg.stream = 0;
            cfg.attrs = pdlAttr;
            cfg.numAttrs = 1;

            const float* Wr = W_root + (size_t)layer * DIM * DIM;
            const float* We = W_rel  + (size_t)layer * DIM * DIM;
            const float* bs = b_rel  + (size_t)layer * DIM;
            int doTanh = (layer == NLAYERS - 1) ? 1 : 0;
            cudaLaunchKernelEx(&cfg, gemm_tc_kernel,
                               hprev, pAgg, Wr, We, bs, hnext, doTanh);
        }

        hprev = hnext;
    }
}